// round 3
// baseline (speedup 1.0000x reference)
#include <cuda_runtime.h>
#include <cuda_bf16.h>
#include <math.h>

// Problem constants (from reference)
#define NFEAT   256
#define NHID    64
#define NCLASS  16
#define MAXN    50000

// Scratch (allocation-free: static device globals). 16B-aligned for float4 / red.v4.
__device__ __align__(16) float g_S1[MAXN * NHID];    // x @ W1            [N,64]
__device__ __align__(16) float g_H [MAXN * NHID];    // spmm1 + b1 accum  [N,64]
__device__ __align__(16) float g_S2[MAXN * NCLASS];  // relu(h) @ W2      [N,16]
__device__ __align__(16) float g_O [MAXN * NCLASS];  // spmm2 + b2 accum  [N,16]

// ---------------------------------------------------------------------------
// GEMM1: S1[N,64] = x[N,256] @ W1[256,64]
// Block: 256 threads -> 64-row x 64-col tile, 4x4 register blocking per thread.
// k-chunks of 32 staged in smem.
// ---------------------------------------------------------------------------
__global__ void __launch_bounds__(256) gemm1_kernel(
    const float* __restrict__ x, const float* __restrict__ W1, int n_nodes)
{
    __shared__ float xs[64][33];   // [row][k], padded: rows 128 apart would bank-alias
    __shared__ float ws[32][64];   // [k][col], float4-friendly

    const int tid = threadIdx.x;
    const int tx = tid & 15;        // col group: cols 4*tx .. 4*tx+3
    const int ty = tid >> 4;        // row group: rows 4*ty .. 4*ty+3
    const int rowBase = blockIdx.x * 64;

    float acc[4][4];
#pragma unroll
    for (int i = 0; i < 4; i++)
#pragma unroll
        for (int j = 0; j < 4; j++) acc[i][j] = 0.f;

#pragma unroll 1
    for (int k0 = 0; k0 < NFEAT; k0 += 32) {
        // Load x tile: 64 rows x 32 k = 512 float4 slots; 2 per thread
#pragma unroll
        for (int j = 0; j < 2; j++) {
            int s = tid * 2 + j;          // 0..511
            int r = s >> 3;               // 0..63
            int c4 = s & 7;               // 0..7
            float4 v = make_float4(0.f, 0.f, 0.f, 0.f);
            int grow = rowBase + r;
            if (grow < n_nodes)
                v = *reinterpret_cast<const float4*>(&x[grow * NFEAT + k0 + c4 * 4]);
            xs[r][c4 * 4 + 0] = v.x;
            xs[r][c4 * 4 + 1] = v.y;
            xs[r][c4 * 4 + 2] = v.z;
            xs[r][c4 * 4 + 3] = v.w;
        }
        // Load W1 tile: 32 k x 64 cols = 512 float4 slots; 2 per thread
#pragma unroll
        for (int j = 0; j < 2; j++) {
            int s = tid * 2 + j;          // 0..511
            int kk = s >> 4;              // 0..31
            int c4 = s & 15;              // 0..15
            float4 v = *reinterpret_cast<const float4*>(&W1[(k0 + kk) * NHID + c4 * 4]);
            *reinterpret_cast<float4*>(&ws[kk][c4 * 4]) = v;
        }
        __syncthreads();

#pragma unroll
        for (int kk = 0; kk < 32; kk++) {
            float4 w = *reinterpret_cast<const float4*>(&ws[kk][4 * tx]);
            float a0 = xs[4 * ty + 0][kk];
            float a1 = xs[4 * ty + 1][kk];
            float a2 = xs[4 * ty + 2][kk];
            float a3 = xs[4 * ty + 3][kk];
            acc[0][0] += a0 * w.x; acc[0][1] += a0 * w.y; acc[0][2] += a0 * w.z; acc[0][3] += a0 * w.w;
            acc[1][0] += a1 * w.x; acc[1][1] += a1 * w.y; acc[1][2] += a1 * w.z; acc[1][3] += a1 * w.w;
            acc[2][0] += a2 * w.x; acc[2][1] += a2 * w.y; acc[2][2] += a2 * w.z; acc[2][3] += a2 * w.w;
            acc[3][0] += a3 * w.x; acc[3][1] += a3 * w.y; acc[3][2] += a3 * w.z; acc[3][3] += a3 * w.w;
        }
        __syncthreads();
    }

#pragma unroll
    for (int i = 0; i < 4; i++) {
        int grow = rowBase + 4 * ty + i;
        if (grow < n_nodes) {
            float4 v = make_float4(acc[i][0], acc[i][1], acc[i][2], acc[i][3]);
            *reinterpret_cast<float4*>(&g_S1[grow * NHID + 4 * tx]) = v;
        }
    }
}

// ---------------------------------------------------------------------------
// Init H with b1 broadcast (so spmm1 is pure scatter-add)
// ---------------------------------------------------------------------------
__global__ void init_h_kernel(const float* __restrict__ b1, int n_nodes)
{
    int idx = blockIdx.x * blockDim.x + threadIdx.x;
    int total = n_nodes * NHID;
    if (idx < total) g_H[idx] = b1[idx & (NHID - 1)];
}

// ---------------------------------------------------------------------------
// SpMM1: H[dst] += w * S1[src]   (64 floats/edge; 16 threads/edge, float4 each)
// ---------------------------------------------------------------------------
__global__ void __launch_bounds__(256) spmm1_kernel(
    const int* __restrict__ src, const int* __restrict__ dst,
    const float* __restrict__ ew, int n_edges)
{
    long long t = (long long)blockIdx.x * blockDim.x + threadIdx.x;
    int e = (int)(t >> 4);
    if (e >= n_edges) return;
    int lane = (int)(t & 15);
    int s = src[e];
    int d = dst[e];
    float w = ew[e];
    float4 v = *reinterpret_cast<const float4*>(&g_S1[s * NHID + lane * 4]);
    float mx = v.x * w, my = v.y * w, mz = v.z * w, mw = v.w * w;
    float* p = &g_H[d * NHID + lane * 4];
    asm volatile("red.global.add.v4.f32 [%0], {%1, %2, %3, %4};"
                 :: "l"(p), "f"(mx), "f"(my), "f"(mz), "f"(mw) : "memory");
}

// ---------------------------------------------------------------------------
// GEMM2 fused ReLU: S2[N,16] = relu(H)[N,64] @ W2[64,16]
// Block: 256 threads -> 16 rows, each thread = (row, col)
// ---------------------------------------------------------------------------
__global__ void __launch_bounds__(256) gemm2_kernel(
    const float* __restrict__ W2, int n_nodes)
{
    __shared__ float hs[16][65];   // padded: warp rows 64 apart would bank-alias
    __shared__ float ws2[64][16];

    const int tid = threadIdx.x;
    const int col = tid & 15;
    const int row = tid >> 4;
    const int rowBase = blockIdx.x * 16;

    // Load H tile: 16 rows x 64 = 256 float4 slots; 1 per thread
    {
        int r = tid >> 4;        // 0..15
        int c4 = tid & 15;       // 0..15
        float4 v = make_float4(0.f, 0.f, 0.f, 0.f);
        int grow = rowBase + r;
        if (grow < n_nodes)
            v = *reinterpret_cast<const float4*>(&g_H[grow * NHID + c4 * 4]);
        hs[r][c4 * 4 + 0] = v.x;
        hs[r][c4 * 4 + 1] = v.y;
        hs[r][c4 * 4 + 2] = v.z;
        hs[r][c4 * 4 + 3] = v.w;
    }
    // Load W2: 64x16 = 256 float4 slots; 1 per thread
    {
        int kk = tid >> 2;       // 0..63
        int c4 = tid & 3;        // 0..3
        float4 v = *reinterpret_cast<const float4*>(&W2[kk * NCLASS + c4 * 4]);
        *reinterpret_cast<float4*>(&ws2[kk][c4 * 4]) = v;
    }
    __syncthreads();

    float acc = 0.f;
#pragma unroll
    for (int k = 0; k < NHID; k++)
        acc += fmaxf(hs[row][k], 0.f) * ws2[k][col];

    int grow = rowBase + row;
    if (grow < n_nodes) g_S2[grow * NCLASS + col] = acc;
}

// ---------------------------------------------------------------------------
// Init O with b2 broadcast
// ---------------------------------------------------------------------------
__global__ void init_o_kernel(const float* __restrict__ b2, int n_nodes)
{
    int idx = blockIdx.x * blockDim.x + threadIdx.x;
    int total = n_nodes * NCLASS;
    if (idx < total) g_O[idx] = b2[idx & (NCLASS - 1)];
}

// ---------------------------------------------------------------------------
// SpMM2: O[dst] += w * S2[src]   (16 floats/edge; 4 threads/edge, float4 each)
// ---------------------------------------------------------------------------
__global__ void __launch_bounds__(256) spmm2_kernel(
    const int* __restrict__ src, const int* __restrict__ dst,
    const float* __restrict__ ew, int n_edges)
{
    long long t = (long long)blockIdx.x * blockDim.x + threadIdx.x;
    int e = (int)(t >> 2);
    if (e >= n_edges) return;
    int q = (int)(t & 3);
    int s = src[e];
    int d = dst[e];
    float w = ew[e];
    float4 v = *reinterpret_cast<const float4*>(&g_S2[s * NCLASS + q * 4]);
    float mx = v.x * w, my = v.y * w, mz = v.z * w, mw = v.w * w;
    float* p = &g_O[d * NCLASS + q * 4];
    asm volatile("red.global.add.v4.f32 [%0], {%1, %2, %3, %4};"
                 :: "l"(p), "f"(mx), "f"(my), "f"(mz), "f"(mw) : "memory");
}

// ---------------------------------------------------------------------------
// log_softmax over 16 classes, one thread per row
// ---------------------------------------------------------------------------
__global__ void logsoftmax_kernel(float* __restrict__ out, int n_nodes)
{
    int i = blockIdx.x * blockDim.x + threadIdx.x;
    if (i >= n_nodes) return;
    float v[NCLASS];
#pragma unroll
    for (int j = 0; j < 4; j++) {
        float4 t = *reinterpret_cast<const float4*>(&g_O[i * NCLASS + j * 4]);
        v[j * 4 + 0] = t.x; v[j * 4 + 1] = t.y; v[j * 4 + 2] = t.z; v[j * 4 + 3] = t.w;
    }
    float m = v[0];
#pragma unroll
    for (int j = 1; j < NCLASS; j++) m = fmaxf(m, v[j]);
    float sum = 0.f;
#pragma unroll
    for (int j = 0; j < NCLASS; j++) sum += expf(v[j] - m);
    float lse = logf(sum);
#pragma unroll
    for (int j = 0; j < 4; j++) {
        float4 t = make_float4(v[j * 4 + 0] - m - lse, v[j * 4 + 1] - m - lse,
                               v[j * 4 + 2] - m - lse, v[j * 4 + 3] - m - lse);
        *reinterpret_cast<float4*>(&out[i * NCLASS + j * 4]) = t;
    }
}

// ---------------------------------------------------------------------------
// Launch
// Inputs (metadata order): x, W1, b1, W2, b2, edge_src, edge_dst, edge_weight
// ---------------------------------------------------------------------------
extern "C" void kernel_launch(void* const* d_in, const int* in_sizes, int n_in,
                              void* d_out, int out_size)
{
    const float* x   = (const float*)d_in[0];
    const float* W1  = (const float*)d_in[1];
    const float* b1  = (const float*)d_in[2];
    const float* W2  = (const float*)d_in[3];
    const float* b2  = (const float*)d_in[4];
    const int*   esrc = (const int*)d_in[5];
    const int*   edst = (const int*)d_in[6];
    const float* ew  = (const float*)d_in[7];

    int n_nodes = in_sizes[0] / NFEAT;
    int n_edges = in_sizes[5];

    // Layer 1
    gemm1_kernel<<<(n_nodes + 63) / 64, 256>>>(x, W1, n_nodes);
    init_h_kernel<<<(n_nodes * NHID + 255) / 256, 256>>>(b1, n_nodes);
    {
        long long threads = (long long)n_edges * 16;
        int blocks = (int)((threads + 255) / 256);
        spmm1_kernel<<<blocks, 256>>>(esrc, edst, ew, n_edges);
    }

    // Layer 2
    gemm2_kernel<<<(n_nodes + 15) / 16, 256>>>(W2, n_nodes);
    init_o_kernel<<<(n_nodes * NCLASS + 255) / 256, 256>>>(b2, n_nodes);
    {
        long long threads = (long long)n_edges * 4;
        int blocks = (int)((threads + 255) / 256);
        spmm2_kernel<<<blocks, 256>>>(esrc, edst, ew, n_edges);
    }

    // Output
    logsoftmax_kernel<<<(n_nodes + 255) / 256, 256>>>((float*)d_out, n_nodes);
}